// round 2
// baseline (speedup 1.0000x reference)
#include <cuda_runtime.h>

#define NB    8
#define BATCH 65536
#define SEQ   54
#define DIM   6
#define EPS   1e-5f

// ---------------- shared layout (in floats) ----------------
// All weight rows padded to 8 floats so a row = float4 + float2 (16B aligned).
#define S_EW 0        // embed_w  [6][8]           -> 48
#define S_EB 48       // embed_b  [8]              -> 56
#define S_FW 56       // fc1_w    [8][6][8]  (384) -> 440
#define S_FB 440      // fc1_b    [8][8]     (64)  -> 504
#define S_LG 504      // ln_g     [8][8]     (64)  -> 568
#define S_LB 568      // ln_b     [8][8]     (64)  -> 632
#define S_IW 632      // inproj_w [8][18][8] (1152)-> 1784
#define S_IB 1784     // inproj_b [8][18]    (144) -> 1928
#define S_OW 1928     // out_w    [8][6][8]  (384) -> 2312
#define S_OB 2312     // out_b    [8][8]     (64)  -> 2376
#define S_KV 2376     // per-warp k[54][8]+v[54][8] = 864 floats * 8 warps = 6912
#define S_TOTAL (S_KV + 8 * 864)   // 9288 floats = 37152 B

__device__ __forceinline__ float dot6(const float* __restrict__ w, const float h[6]) {
    float4 w4 = *(const float4*)w;
    float2 w2 = *(const float2*)(w + 4);
    return h[0]*w4.x + h[1]*w4.y + h[2]*w4.z + h[3]*w4.w + h[4]*w2.x + h[5]*w2.y;
}

__device__ __forceinline__ float elu(float t) {
    return t > 0.f ? t : (__expf(t) - 1.f);
}

// fc1 + ELU + LayerNorm + qkv projection for one row (all register-resident).
// q is pre-scaled by 1/sqrt(DIM); k,v rows stored to shared if `store`.
__device__ __forceinline__ void block_row(
    const float h[6], float q[6],
    float* __restrict__ ks, float* __restrict__ vs, int r, bool store,
    const float* __restrict__ fwb, const float* __restrict__ fbb,
    const float* __restrict__ lgb, const float* __restrict__ lbb,
    const float* __restrict__ iwb, const float* __restrict__ ibb)
{
    float z[6];
    #pragma unroll
    for (int d = 0; d < 6; d++) {
        float t = fbb[d] + dot6(fwb + d*8, h);
        z[d] = elu(t);
    }
    float mu = (z[0]+z[1]+z[2]+z[3]+z[4]+z[5]) * (1.0f/6.0f);
    float var = 0.f;
    #pragma unroll
    for (int d = 0; d < 6; d++) { float t = z[d] - mu; var = fmaf(t, t, var); }
    float is = rsqrtf(var * (1.0f/6.0f) + EPS);
    #pragma unroll
    for (int d = 0; d < 6; d++) z[d] = (z[d] - mu) * is * lgb[d] + lbb[d];

    const float inv = 0.40824829046386302f;  // 1/sqrt(6)
    #pragma unroll
    for (int j = 0; j < 6; j++) q[j] = (ibb[j] + dot6(iwb + j*8, z)) * inv;

    float kr[6], vr[6];
    #pragma unroll
    for (int j = 0; j < 6; j++) kr[j] = ibb[6 + j]  + dot6(iwb + (6 + j)*8,  z);
    #pragma unroll
    for (int j = 0; j < 6; j++) vr[j] = ibb[12 + j] + dot6(iwb + (12 + j)*8, z);

    if (store) {
        *(float4*)(ks + r*8)     = make_float4(kr[0], kr[1], kr[2], kr[3]);
        *(float2*)(ks + r*8 + 4) = make_float2(kr[4], kr[5]);
        *(float4*)(vs + r*8)     = make_float4(vr[0], vr[1], vr[2], vr[3]);
        *(float2*)(vs + r*8 + 4) = make_float2(vr[4], vr[5]);
    }
}

__global__ __launch_bounds__(256)
void rubik_kernel(const float* __restrict__ x,
                  const float* __restrict__ ew, const float* __restrict__ eb,
                  const float* __restrict__ fw, const float* __restrict__ fb,
                  const float* __restrict__ lg, const float* __restrict__ lb,
                  const float* __restrict__ iw, const float* __restrict__ ib,
                  const float* __restrict__ ow, const float* __restrict__ ob,
                  const float* __restrict__ vw, const float* __restrict__ vb,
                  const float* __restrict__ pw, const float* __restrict__ pb,
                  float* __restrict__ out)
{
    __shared__ __align__(16) float s[S_TOTAL];
    const int tid = threadIdx.x;

    // ---- stage weights into padded shared layout (once per CTA) ----
    for (int t = tid; t < 36;  t += 256) s[S_EW + (t/6)*8 + t%6] = ew[t];
    for (int t = tid; t < 6;   t += 256) s[S_EB + t] = eb[t];
    for (int t = tid; t < 288; t += 256) { int b = t/36; s[S_FW + b*48 + ((t/6)%6)*8 + t%6] = fw[t]; }
    for (int t = tid; t < 48;  t += 256) s[S_FB + (t/6)*8 + t%6] = fb[t];
    for (int t = tid; t < 48;  t += 256) s[S_LG + (t/6)*8 + t%6] = lg[t];
    for (int t = tid; t < 48;  t += 256) s[S_LB + (t/6)*8 + t%6] = lb[t];
    for (int t = tid; t < 864; t += 256) { int b = t/108; s[S_IW + b*144 + ((t/6)%18)*8 + t%6] = iw[t]; }
    for (int t = tid; t < 144; t += 256) s[S_IB + t] = ib[t];
    for (int t = tid; t < 288; t += 256) { int b = t/36; s[S_OW + b*48 + ((t/6)%6)*8 + t%6] = ow[t]; }
    for (int t = tid; t < 48;  t += 256) s[S_OB + (t/6)*8 + t%6] = ob[t];
    __syncthreads();

    const int warp = tid >> 5, lane = tid & 31;
    const int bi   = blockIdx.x * 8 + warp;         // batch element for this warp
    float* ks = s + S_KV + warp * 864;
    float* vs = ks + 432;

    const int  r0   = lane;
    const int  r1   = lane + 32;
    const bool has2 = (r1 < SEQ);

    // ---- load x rows, apply embed (row-wise 6x6 matmul) ----
    float xr0[6], xr1[6];
    {
        const float* p0 = x + (size_t)bi * (SEQ*DIM) + r0 * DIM;
        float2 a = *(const float2*)(p0), b2 = *(const float2*)(p0+2), c = *(const float2*)(p0+4);
        xr0[0]=a.x; xr0[1]=a.y; xr0[2]=b2.x; xr0[3]=b2.y; xr0[4]=c.x; xr0[5]=c.y;
    }
    if (has2) {
        const float* p1 = x + (size_t)bi * (SEQ*DIM) + r1 * DIM;
        float2 a = *(const float2*)(p1), b2 = *(const float2*)(p1+2), c = *(const float2*)(p1+4);
        xr1[0]=a.x; xr1[1]=a.y; xr1[2]=b2.x; xr1[3]=b2.y; xr1[4]=c.x; xr1[5]=c.y;
    } else {
        #pragma unroll
        for (int d = 0; d < 6; d++) xr1[d] = 0.f;
    }

    float h0[6], h1[6];
    #pragma unroll
    for (int d = 0; d < 6; d++) {
        h0[d] = s[S_EB + d] + dot6(s + S_EW + d*8, xr0);
        h1[d] = s[S_EB + d] + dot6(s + S_EW + d*8, xr1);
    }

    // ---- 8 transformer blocks ----
    for (int b = 0; b < NB; b++) {
        const float* fwb = s + S_FW + b*48;
        const float* fbb = s + S_FB + b*8;
        const float* lgb = s + S_LG + b*8;
        const float* lbb = s + S_LB + b*8;
        const float* iwb = s + S_IW + b*144;
        const float* ibb = s + S_IB + b*18;
        const float* owb = s + S_OW + b*48;
        const float* obb = s + S_OB + b*8;

        __syncwarp();   // previous block's k/v reads done before overwrite
        float q0[6], q1[6];
        block_row(h0, q0, ks, vs, r0, true,  fwb, fbb, lgb, lbb, iwb, ibb);
        if (has2) {
            block_row(h1, q1, ks, vs, r1, true, fwb, fbb, lgb, lbb, iwb, ibb);
        } else {
            #pragma unroll
            for (int j = 0; j < 6; j++) q1[j] = 0.f;
        }
        __syncwarp();   // k/v tiles complete

        // online softmax-attention, no max-subtraction (scores provably bounded:
        // LN gives |z|<=sqrt(5), so exp can't overflow; softmax is shift-invariant)
        float l0 = 0.f, l1 = 0.f;
        float a0[6] = {0,0,0,0,0,0}, a1[6] = {0,0,0,0,0,0};
        #pragma unroll 6
        for (int kk = 0; kk < SEQ; kk++) {
            const float4 k4 = *(const float4*)(ks + kk*8);
            const float2 k2 = *(const float2*)(ks + kk*8 + 4);
            const float4 v4 = *(const float4*)(vs + kk*8);
            const float2 v2 = *(const float2*)(vs + kk*8 + 4);
            // two independent dependency chains into the two MUFUs
            float s0 = fmaf(q0[0], k4.x, q0[1]*k4.y);
            float s1 = fmaf(q1[0], k4.x, q1[1]*k4.y);
            s0 = fmaf(q0[2], k4.z, s0); s1 = fmaf(q1[2], k4.z, s1);
            s0 = fmaf(q0[3], k4.w, s0); s1 = fmaf(q1[3], k4.w, s1);
            s0 = fmaf(q0[4], k2.x, s0); s1 = fmaf(q1[4], k2.x, s1);
            s0 = fmaf(q0[5], k2.y, s0); s1 = fmaf(q1[5], k2.y, s1);
            float e0 = __expf(s0);
            float e1 = __expf(s1);
            l0 += e0;  l1 += e1;
            a0[0] = fmaf(e0, v4.x, a0[0]); a1[0] = fmaf(e1, v4.x, a1[0]);
            a0[1] = fmaf(e0, v4.y, a0[1]); a1[1] = fmaf(e1, v4.y, a1[1]);
            a0[2] = fmaf(e0, v4.z, a0[2]); a1[2] = fmaf(e1, v4.z, a1[2]);
            a0[3] = fmaf(e0, v4.w, a0[3]); a1[3] = fmaf(e1, v4.w, a1[3]);
            a0[4] = fmaf(e0, v2.x, a0[4]); a1[4] = fmaf(e1, v2.x, a1[4]);
            a0[5] = fmaf(e0, v2.y, a0[5]); a1[5] = fmaf(e1, v2.y, a1[5]);
        }

        // out projection + ELU + residual
        {
            float rl = __fdividef(1.f, l0);
            float o[6];
            #pragma unroll
            for (int d = 0; d < 6; d++) o[d] = a0[d] * rl;
            #pragma unroll
            for (int d = 0; d < 6; d++) {
                float t = obb[d] + dot6(owb + d*8, o);
                h0[d] += elu(t);
            }
        }
        if (has2) {
            float rl = __fdividef(1.f, l1);
            float o[6];
            #pragma unroll
            for (int d = 0; d < 6; d++) o[d] = a1[d] * rl;
            #pragma unroll
            for (int d = 0; d < 6; d++) {
                float t = obb[d] + dot6(owb + d*8, o);
                h1[d] += elu(t);
            }
        }
    }

    // ---- heads: f = h.reshape(324); v = f@vw^T + vb; p = softmax(f@pw^T + pb) ----
    __syncwarp();
    float* fs = ks;   // reuse per-warp k tile (432 floats >= 324)
    #pragma unroll
    for (int d = 0; d < 6; d++) fs[r0*6 + d] = h0[d];
    if (has2) {
        #pragma unroll
        for (int d = 0; d < 6; d++) fs[r1*6 + d] = h1[d];
    }
    __syncwarp();

    float av = 0.f;
    float ap[12] = {0,0,0,0,0,0,0,0,0,0,0,0};
    for (int i = lane; i < SEQ*DIM; i += 32) {
        float fv = fs[i];
        av = fmaf(fv, __ldg(vw + i), av);
        #pragma unroll
        for (int j = 0; j < 12; j++) ap[j] = fmaf(fv, __ldg(pw + j*(SEQ*DIM) + i), ap[j]);
    }
    #pragma unroll
    for (int off = 16; off > 0; off >>= 1) {
        av += __shfl_xor_sync(0xffffffffu, av, off);
        #pragma unroll
        for (int j = 0; j < 12; j++) ap[j] += __shfl_xor_sync(0xffffffffu, ap[j], off);
    }
    av += __ldg(vb);
    #pragma unroll
    for (int j = 0; j < 12; j++) ap[j] += __ldg(pb + j);

    float m = ap[0];
    #pragma unroll
    for (int j = 1; j < 12; j++) m = fmaxf(m, ap[j]);
    float sum = 0.f;
    #pragma unroll
    for (int j = 0; j < 12; j++) sum += __expf(ap[j] - m);
    float rs = __fdividef(1.f, sum);

    if (lane == 0) out[bi] = av;
    float mine = 0.f;
    #pragma unroll
    for (int j = 0; j < 12; j++) if (lane == j) mine = ap[j];
    if (lane < 12) out[BATCH + (size_t)bi*12 + lane] = __expf(mine - m) * rs;
}

extern "C" void kernel_launch(void* const* d_in, const int* in_sizes, int n_in,
                              void* d_out, int out_size)
{
    (void)in_sizes; (void)n_in; (void)out_size;
    const float* x  = (const float*)d_in[0];
    const float* ew = (const float*)d_in[1];
    const float* eb = (const float*)d_in[2];
    const float* fw = (const float*)d_in[3];
    const float* fb = (const float*)d_in[4];
    const float* lg = (const float*)d_in[5];
    const float* lb = (const float*)d_in[6];
    const float* iw = (const float*)d_in[7];
    const float* ib = (const float*)d_in[8];
    const float* ow = (const float*)d_in[9];
    const float* ob = (const float*)d_in[10];
    const float* vw = (const float*)d_in[11];
    const float* vb = (const float*)d_in[12];
    const float* pw = (const float*)d_in[13];
    const float* pb = (const float*)d_in[14];
    float* out = (float*)d_out;

    rubik_kernel<<<BATCH/8, 256>>>(x, ew, eb, fw, fb, lg, lb,
                                   iw, ib, ow, ob, vw, vb, pw, pb, out);
}

// round 4
// speedup vs baseline: 1.2326x; 1.2326x over previous
#include <cuda_runtime.h>

#define NB    8
#define BATCH 65536
#define SEQ   54
#define DIM   6
#define EPS   1e-5f

// ---------------- shared layout (in floats) ----------------
// Weight rows padded to 8 floats so a row = float4 + float2 (16B aligned).
#define S_EW 0        // embed_w  [6][8]           -> 48
#define S_EB 48       // embed_b  [8]              -> 56
#define S_FW 56       // fc1_w    [8][6][8]  (384) -> 440
#define S_FB 440      // fc1_b    [8][8]     (64)  -> 504
#define S_LG 504      // ln_g     [8][8]     (64)  -> 568
#define S_LB 568      // ln_b     [8][8]     (64)  -> 632
#define S_IW 632      // inproj_w [8][18][8] (1152)-> 1784
#define S_IB 1784     // inproj_b [8][18]    (144) -> 1928
#define S_OW 1928     // out_w    [8][6][8]  (384) -> 2312
#define S_OB 2312     // out_b    [8][8]     (64)  -> 2376
#define S_KV 2376     // 8 tiles of TSTRIDE floats; tile = kv-packed [54][12]
#define TSTRIDE 664   // 54*12=648, +16 pad -> stride%32==24 (conflict-free x-group bcast)
#define S_TOTAL (S_KV + 8 * TSTRIDE)   // 7688 floats = 30752 B

__device__ __forceinline__ float dot6(const float* __restrict__ w, const float h[6]) {
    float4 w4 = *(const float4*)w;
    float2 w2 = *(const float2*)(w + 4);
    return h[0]*w4.x + h[1]*w4.y + h[2]*w4.z + h[3]*w4.w + h[4]*w2.x + h[5]*w2.y;
}

__device__ __forceinline__ float ex2(float x) {
    float y;
    asm("ex2.approx.ftz.f32 %0, %1;" : "=f"(y) : "f"(x));
    return y;
}

__device__ __forceinline__ float elu(float t) {
    return t > 0.f ? t : (__expf(t) - 1.f);
}

// fc1 + ELU + LayerNorm + qkv projection for one row.
// q is pre-scaled by log2(e)/sqrt(DIM) (EX2-ready); k||v packed 12 floats at kv.
__device__ __forceinline__ void block_row(
    const float h[6], float q[6], float* __restrict__ kv,
    const float* __restrict__ fwb, const float* __restrict__ fbb,
    const float* __restrict__ lgb, const float* __restrict__ lbb,
    const float* __restrict__ iwb, const float* __restrict__ ibb)
{
    float z[6];
    #pragma unroll
    for (int d = 0; d < 6; d++) {
        float t = fbb[d] + dot6(fwb + d*8, h);
        z[d] = elu(t);
    }
    float mu = (z[0]+z[1]+z[2]+z[3]+z[4]+z[5]) * (1.0f/6.0f);
    float var = 0.f;
    #pragma unroll
    for (int d = 0; d < 6; d++) { float t = z[d] - mu; var = fmaf(t, t, var); }
    float is = rsqrtf(var * (1.0f/6.0f) + EPS);
    #pragma unroll
    for (int d = 0; d < 6; d++) z[d] = (z[d] - mu) * is * lgb[d] + lbb[d];

    const float qs = 0.588978587229f;  // log2(e) / sqrt(6)
    #pragma unroll
    for (int j = 0; j < 6; j++) q[j] = (ibb[j] + dot6(iwb + j*8, z)) * qs;

    float kr[6], vr[6];
    #pragma unroll
    for (int j = 0; j < 6; j++) kr[j] = ibb[6 + j]  + dot6(iwb + (6 + j)*8,  z);
    #pragma unroll
    for (int j = 0; j < 6; j++) vr[j] = ibb[12 + j] + dot6(iwb + (12 + j)*8, z);

    *(float4*)(kv)     = make_float4(kr[0], kr[1], kr[2], kr[3]);
    *(float4*)(kv + 4) = make_float4(kr[4], kr[5], vr[0], vr[1]);
    *(float4*)(kv + 8) = make_float4(vr[2], vr[3], vr[4], vr[5]);
}

__global__ __launch_bounds__(256)
void rubik_kernel(const float* __restrict__ x,
                  const float* __restrict__ ew, const float* __restrict__ eb,
                  const float* __restrict__ fw, const float* __restrict__ fb,
                  const float* __restrict__ lg, const float* __restrict__ lb,
                  const float* __restrict__ iw, const float* __restrict__ ib,
                  const float* __restrict__ ow, const float* __restrict__ ob,
                  const float* __restrict__ vw, const float* __restrict__ vb,
                  const float* __restrict__ pw, const float* __restrict__ pb,
                  float* __restrict__ out)
{
    __shared__ __align__(16) float s[S_TOTAL];
    const int tid = threadIdx.x;

    // ---- stage weights into padded shared layout (once per CTA) ----
    for (int t = tid; t < 36;  t += 256) s[S_EW + (t/6)*8 + t%6] = ew[t];
    for (int t = tid; t < 6;   t += 256) s[S_EB + t] = eb[t];
    for (int t = tid; t < 288; t += 256) { int b = t/36; s[S_FW + b*48 + ((t/6)%6)*8 + t%6] = fw[t]; }
    for (int t = tid; t < 48;  t += 256) s[S_FB + (t/6)*8 + t%6] = fb[t];
    for (int t = tid; t < 48;  t += 256) s[S_LG + (t/6)*8 + t%6] = lg[t];
    for (int t = tid; t < 48;  t += 256) s[S_LB + (t/6)*8 + t%6] = lb[t];
    for (int t = tid; t < 864; t += 256) { int b = t/108; s[S_IW + b*144 + ((t/6)%18)*8 + t%6] = iw[t]; }
    for (int t = tid; t < 144; t += 256) s[S_IB + t] = ib[t];
    for (int t = tid; t < 288; t += 256) { int b = t/36; s[S_OW + b*48 + ((t/6)%6)*8 + t%6] = ow[t]; }
    for (int t = tid; t < 48;  t += 256) s[S_OB + (t/6)*8 + t%6] = ob[t];
    __syncthreads();

    // ---- CTA-wide row-pair mapping: 8 elems x 27 pairs = 216 active threads ----
    const bool act = tid < 216;
    const int  e   = tid / 27;            // element within CTA (0..7)
    const int  pr  = tid % 27;            // pair index
    const int  r0  = pr, r1 = pr + 27;    // two rows of the SAME element
    const int  bie = blockIdx.x * 8 + e;  // global batch index for compute
    float* tile = s + S_KV + e * TSTRIDE; // packed kv tile of this element

    // ---- load x rows, apply embed ----
    float h0[6], h1[6];
    if (act) {
        float xr0[6], xr1[6];
        const float* p0 = x + (size_t)bie * (SEQ*DIM) + r0 * DIM;
        const float* p1 = x + (size_t)bie * (SEQ*DIM) + r1 * DIM;
        {
            float2 a = *(const float2*)(p0), b2 = *(const float2*)(p0+2), c = *(const float2*)(p0+4);
            xr0[0]=a.x; xr0[1]=a.y; xr0[2]=b2.x; xr0[3]=b2.y; xr0[4]=c.x; xr0[5]=c.y;
        }
        {
            float2 a = *(const float2*)(p1), b2 = *(const float2*)(p1+2), c = *(const float2*)(p1+4);
            xr1[0]=a.x; xr1[1]=a.y; xr1[2]=b2.x; xr1[3]=b2.y; xr1[4]=c.x; xr1[5]=c.y;
        }
        #pragma unroll
        for (int d = 0; d < 6; d++) {
            h0[d] = s[S_EB + d] + dot6(s + S_EW + d*8, xr0);
            h1[d] = s[S_EB + d] + dot6(s + S_EW + d*8, xr1);
        }
    }

    // ---- 8 transformer blocks ----
    for (int b = 0; b < NB; b++) {
        const float* fwb = s + S_FW + b*48;
        const float* fbb = s + S_FB + b*8;
        const float* lgb = s + S_LG + b*8;
        const float* lbb = s + S_LB + b*8;
        const float* iwb = s + S_IW + b*144;
        const float* ibb = s + S_IB + b*18;
        const float* owb = s + S_OW + b*48;
        const float* obb = s + S_OB + b*8;

        __syncthreads();   // previous block's tile reads complete before overwrite

        float q0[6], q1[6];
        if (act) {
            block_row(h0, q0, tile + r0*12, fwb, fbb, lgb, lbb, iwb, ibb);
            block_row(h1, q1, tile + r1*12, fwb, fbb, lgb, lbb, iwb, ibb);
        }
        __syncthreads();   // tiles complete

        if (act) {
            // online softmax-attention via EX2 (q pre-scaled by log2e/sqrt(6)).
            // No max-subtraction: LN bounds |z|<=sqrt(5) => scores bounded, EX2 safe.
            float l0 = 0.f, l1 = 0.f;
            float a0[6] = {0,0,0,0,0,0}, a1[6] = {0,0,0,0,0,0};
            #pragma unroll 6
            for (int kk = 0; kk < SEQ; kk++) {
                const float4 A = *(const float4*)(tile + kk*12);
                const float4 B = *(const float4*)(tile + kk*12 + 4);
                const float4 C = *(const float4*)(tile + kk*12 + 8);
                float s0 = fmaf(q0[0], A.x, q0[1]*A.y);
                float s1 = fmaf(q1[0], A.x, q1[1]*A.y);
                s0 = fmaf(q0[2], A.z, s0); s1 = fmaf(q1[2], A.z, s1);
                s0 = fmaf(q0[3], A.w, s0); s1 = fmaf(q1[3], A.w, s1);
                s0 = fmaf(q0[4], B.x, s0); s1 = fmaf(q1[4], B.x, s1);
                s0 = fmaf(q0[5], B.y, s0); s1 = fmaf(q1[5], B.y, s1);
                float e0 = ex2(s0);
                float e1 = ex2(s1);
                l0 += e0;  l1 += e1;
                a0[0] = fmaf(e0, B.z, a0[0]); a1[0] = fmaf(e1, B.z, a1[0]);
                a0[1] = fmaf(e0, B.w, a0[1]); a1[1] = fmaf(e1, B.w, a1[1]);
                a0[2] = fmaf(e0, C.x, a0[2]); a1[2] = fmaf(e1, C.x, a1[2]);
                a0[3] = fmaf(e0, C.y, a0[3]); a1[3] = fmaf(e1, C.y, a1[3]);
                a0[4] = fmaf(e0, C.z, a0[4]); a1[4] = fmaf(e1, C.z, a1[4]);
                a0[5] = fmaf(e0, C.w, a0[5]); a1[5] = fmaf(e1, C.w, a1[5]);
            }

            // out projection + ELU + residual (both rows)
            {
                float rl = __fdividef(1.f, l0);
                float o[6];
                #pragma unroll
                for (int d = 0; d < 6; d++) o[d] = a0[d] * rl;
                #pragma unroll
                for (int d = 0; d < 6; d++) {
                    float t = obb[d] + dot6(owb + d*8, o);
                    h0[d] += elu(t);
                }
            }
            {
                float rl = __fdividef(1.f, l1);
                float o[6];
                #pragma unroll
                for (int d = 0; d < 6; d++) o[d] = a1[d] * rl;
                #pragma unroll
                for (int d = 0; d < 6; d++) {
                    float t = obb[d] + dot6(owb + d*8, o);
                    h1[d] += elu(t);
                }
            }
        }
    }

    // ---- heads: f = h.reshape(324); v = f@vw^T + vb; p = softmax(f@pw^T + pb) ----
    __syncthreads();   // last block's attention reads done before tiles become f-buffers
    if (act) {
        float* fs = tile;                 // reuse this element's tile as f storage
        #pragma unroll
        for (int d = 0; d < 6; d += 2) *(float2*)(fs + r0*6 + d) = make_float2(h0[d], h0[d+1]);
        #pragma unroll
        for (int d = 0; d < 6; d += 2) *(float2*)(fs + r1*6 + d) = make_float2(h1[d], h1[d+1]);
    }
    __syncthreads();

    const int warp = tid >> 5, lane = tid & 31;
    const int bi   = blockIdx.x * 8 + warp;          // warp <-> element for heads
    const float* fs = s + S_KV + warp * TSTRIDE;

    float av = 0.f;
    float ap[12] = {0,0,0,0,0,0,0,0,0,0,0,0};
    for (int i = lane; i < SEQ*DIM; i += 32) {
        float fv = fs[i];
        av = fmaf(fv, __ldg(vw + i), av);
        #pragma unroll
        for (int j = 0; j < 12; j++) ap[j] = fmaf(fv, __ldg(pw + j*(SEQ*DIM) + i), ap[j]);
    }
    #pragma unroll
    for (int off = 16; off > 0; off >>= 1) {
        av += __shfl_xor_sync(0xffffffffu, av, off);
        #pragma unroll
        for (int j = 0; j < 12; j++) ap[j] += __shfl_xor_sync(0xffffffffu, ap[j], off);
    }
    av += __ldg(vb);
    #pragma unroll
    for (int j = 0; j < 12; j++) ap[j] += __ldg(pb + j);

    float m = ap[0];
    #pragma unroll
    for (int j = 1; j < 12; j++) m = fmaxf(m, ap[j]);
    float sum = 0.f;
    #pragma unroll
    for (int j = 0; j < 12; j++) sum += __expf(ap[j] - m);
    float rs = __fdividef(1.f, sum);

    if (lane == 0) out[bi] = av;
    #pragma unroll
    for (int j = 0; j < 12; j++) {
        if (lane == j) out[BATCH + (size_t)bi*12 + j] = __expf(ap[j] - m) * rs;
    }
}

extern "C" void kernel_launch(void* const* d_in, const int* in_sizes, int n_in,
                              void* d_out, int out_size)
{
    (void)in_sizes; (void)n_in; (void)out_size;
    const float* x  = (const float*)d_in[0];
    const float* ew = (const float*)d_in[1];
    const float* eb = (const float*)d_in[2];
    const float* fw = (const float*)d_in[3];
    const float* fb = (const float*)d_in[4];
    const float* lg = (const float*)d_in[5];
    const float* lb = (const float*)d_in[6];
    const float* iw = (const float*)d_in[7];
    const float* ib = (const float*)d_in[8];
    const float* ow = (const float*)d_in[9];
    const float* ob = (const float*)d_in[10];
    const float* vw = (const float*)d_in[11];
    const float* vb = (const float*)d_in[12];
    const float* pw = (const float*)d_in[13];
    const float* pb = (const float*)d_in[14];
    float* out = (float*)d_out;

    rubik_kernel<<<BATCH/8, 256>>>(x, ew, eb, fw, fb, lg, lb,
                                   iw, ib, ow, ob, vw, vb, pw, pb, out);
}

// round 5
// speedup vs baseline: 1.4033x; 1.1385x over previous
#include <cuda_runtime.h>

#define NB      8
#define BATCH   65536
#define SEQ     54
#define DIM     6
#define EPS     1e-5f

#define THREADS 128
#define ELEMS   7            // batch elements per CTA
#define TPE     18           // threads per element (3 rows each: r, r+18, r+36)
#define ACTIVE  (ELEMS*TPE)  // 126

// ---------------- shared layout (floats) ----------------
#define S_EW 0        // embed_w  [6][8]            -> 48
#define S_EB 48       // embed_b  [8]               -> 56
#define S_FW 56       // fc1_w    [8][6][8]   (384) -> 440
#define S_FB 440      // fc1_b    [8][8]      (64)  -> 504
#define S_LG 504      // ln_g     [8][8]      (64)  -> 568
#define S_LB 568      // ln_b     [8][8]      (64)  -> 632
#define S_IW 632      // inproj_w [8][18][8] (1152) -> 1784
#define S_IB 1784     // inproj_b [8][3][8]  (192)  -> 1976  (q/k/v bias rows, 16B-aligned)
#define S_OW 1976     // out_w    [8][6][8]  (384)  -> 2360
#define S_OB 2360     // out_b    [8][8]     (64)   -> 2424
#define S_KV 2424     // 7 tiles of TSTRIDE; tile = kv-packed [54][12]
#define TSTRIDE 664   // 648 + 16 pad; stride%32==24 -> distinct bank groups per warp
#define S_TOTAL (S_KV + ELEMS * TSTRIDE)   // 7072 floats = 28288 B

__device__ __forceinline__ void ldvec6(const float* __restrict__ p, float v[6]) {
    float4 a = *(const float4*)p;
    float2 b = *(const float2*)(p + 4);
    v[0]=a.x; v[1]=a.y; v[2]=a.z; v[3]=a.w; v[4]=b.x; v[5]=b.y;
}

__device__ __forceinline__ float dot6r(const float w[6], const float h[6]) {
    float t = w[0]*h[0];
    t = fmaf(w[1], h[1], t);
    t = fmaf(w[2], h[2], t);
    t = fmaf(w[3], h[3], t);
    t = fmaf(w[4], h[4], t);
    t = fmaf(w[5], h[5], t);
    return t;
}

__device__ __forceinline__ float ex2(float x) {
    float y;
    asm("ex2.approx.ftz.f32 %0, %1;" : "=f"(y) : "f"(x));
    return y;
}

__device__ __forceinline__ float elu(float t) {
    return t > 0.f ? t : (__expf(t) - 1.f);
}

__device__ __forceinline__ void ln_row(float z[6], const float g[6], const float b[6]) {
    float mu = (z[0]+z[1]+z[2]+z[3]+z[4]+z[5]) * (1.0f/6.0f);
    float var = 0.f;
    #pragma unroll
    for (int d = 0; d < 6; d++) { float t = z[d] - mu; var = fmaf(t, t, var); }
    float is = rsqrtf(var * (1.0f/6.0f) + EPS);
    #pragma unroll
    for (int d = 0; d < 6; d++) z[d] = (z[d] - mu) * is * g[d] + b[d];
}

__global__ __launch_bounds__(THREADS, 4)
void rubik_kernel(const float* __restrict__ x,
                  const float* __restrict__ ew, const float* __restrict__ eb,
                  const float* __restrict__ fw, const float* __restrict__ fb,
                  const float* __restrict__ lg, const float* __restrict__ lb,
                  const float* __restrict__ iw, const float* __restrict__ ib,
                  const float* __restrict__ ow, const float* __restrict__ ob,
                  const float* __restrict__ vw, const float* __restrict__ vb,
                  const float* __restrict__ pw, const float* __restrict__ pb,
                  float* __restrict__ out)
{
    __shared__ __align__(16) float s[S_TOTAL];
    const int tid = threadIdx.x;

    // ---- stage weights into padded shared layout ----
    for (int t = tid; t < 36;  t += THREADS) s[S_EW + (t/6)*8 + t%6] = ew[t];
    for (int t = tid; t < 6;   t += THREADS) s[S_EB + t] = eb[t];
    for (int t = tid; t < 288; t += THREADS) { int b = t/36; s[S_FW + b*48 + ((t/6)%6)*8 + t%6] = fw[t]; }
    for (int t = tid; t < 48;  t += THREADS) s[S_FB + (t/6)*8 + t%6] = fb[t];
    for (int t = tid; t < 48;  t += THREADS) s[S_LG + (t/6)*8 + t%6] = lg[t];
    for (int t = tid; t < 48;  t += THREADS) s[S_LB + (t/6)*8 + t%6] = lb[t];
    for (int t = tid; t < 864; t += THREADS) { int b = t/108; s[S_IW + b*144 + ((t/6)%18)*8 + t%6] = iw[t]; }
    for (int t = tid; t < 144; t += THREADS) { int b = t/18, j = t%18; s[S_IB + b*24 + (j/6)*8 + j%6] = ib[t]; }
    for (int t = tid; t < 288; t += THREADS) { int b = t/36; s[S_OW + b*48 + ((t/6)%6)*8 + t%6] = ow[t]; }
    for (int t = tid; t < 48;  t += THREADS) s[S_OB + (t/6)*8 + t%6] = ob[t];
    __syncthreads();

    // ---- mapping: 7 elems x 18 threads; each thread owns rows r, r+18, r+36 ----
    const bool act = tid < ACTIVE;
    const int  e   = tid / TPE;
    const int  r0  = tid % TPE, r1 = r0 + 18, r2 = r0 + 36;
    const int  bie = blockIdx.x * ELEMS + e;
    const bool valid = act && (bie < BATCH);
    float* tile = s + S_KV + e * TSTRIDE;

    // ---- load x rows + embed (weight-row-major, shared across the 3 rows) ----
    float h0[6], h1[6], h2[6];
    {
        float xr0[6], xr1[6], xr2[6];
        if (valid) {
            const float* p = x + (size_t)bie * (SEQ*DIM);
            ldvec6(p + r0*DIM, xr0);   // 24B load, 8B-aligned: use float2s instead
        }
        // note: x rows are only 8B aligned (6 floats). Do float2 loads explicitly.
        if (valid) {
            const float* p0 = x + (size_t)bie * (SEQ*DIM) + r0*DIM;
            const float* p1 = x + (size_t)bie * (SEQ*DIM) + r1*DIM;
            const float* p2 = x + (size_t)bie * (SEQ*DIM) + r2*DIM;
            float2 a, b, c;
            a = *(const float2*)(p0); b = *(const float2*)(p0+2); c = *(const float2*)(p0+4);
            xr0[0]=a.x; xr0[1]=a.y; xr0[2]=b.x; xr0[3]=b.y; xr0[4]=c.x; xr0[5]=c.y;
            a = *(const float2*)(p1); b = *(const float2*)(p1+2); c = *(const float2*)(p1+4);
            xr1[0]=a.x; xr1[1]=a.y; xr1[2]=b.x; xr1[3]=b.y; xr1[4]=c.x; xr1[5]=c.y;
            a = *(const float2*)(p2); b = *(const float2*)(p2+2); c = *(const float2*)(p2+4);
            xr2[0]=a.x; xr2[1]=a.y; xr2[2]=b.x; xr2[3]=b.y; xr2[4]=c.x; xr2[5]=c.y;
        } else {
            #pragma unroll
            for (int d = 0; d < 6; d++) { xr0[d]=0.f; xr1[d]=0.f; xr2[d]=0.f; }
        }
        float ebv[6]; ldvec6(s + S_EB, ebv);
        #pragma unroll
        for (int j = 0; j < 6; j++) {
            float w[6]; ldvec6(s + S_EW + j*8, w);
            h0[j] = ebv[j] + dot6r(w, xr0);
            h1[j] = ebv[j] + dot6r(w, xr1);
            h2[j] = ebv[j] + dot6r(w, xr2);
        }
    }

    // ---- 8 transformer blocks ----
    for (int b = 0; b < NB; b++) {
        const float* fwb = s + S_FW + b*48;
        const float* iwb = s + S_IW + b*144;
        const float* owb = s + S_OW + b*48;

        __syncthreads();   // prior block's tile reads done before overwrite

        float q0[6], q1[6], q2[6];
        if (act) {
            // fc1 + ELU (weight-row-major over 3 rows)
            float z0[6], z1[6], z2[6];
            {
                float bf[6]; ldvec6(s + S_FB + b*8, bf);
                #pragma unroll
                for (int j = 0; j < 6; j++) {
                    float w[6]; ldvec6(fwb + j*8, w);
                    z0[j] = elu(bf[j] + dot6r(w, h0));
                    z1[j] = elu(bf[j] + dot6r(w, h1));
                    z2[j] = elu(bf[j] + dot6r(w, h2));
                }
            }
            // LayerNorm
            {
                float g[6], bl[6];
                ldvec6(s + S_LG + b*8, g);
                ldvec6(s + S_LB + b*8, bl);
                ln_row(z0, g, bl); ln_row(z1, g, bl); ln_row(z2, g, bl);
            }
            // q projection (pre-scaled by log2e/sqrt(6) for EX2)
            {
                const float qs = 0.588978587229f;
                float bq[6]; ldvec6(s + S_IB + b*24, bq);
                #pragma unroll
                for (int j = 0; j < 6; j++) {
                    float w[6]; ldvec6(iwb + j*8, w);
                    q0[j] = (bq[j] + dot6r(w, z0)) * qs;
                    q1[j] = (bq[j] + dot6r(w, z1)) * qs;
                    q2[j] = (bq[j] + dot6r(w, z2)) * qs;
                }
            }
            // k projection -> store rows
            {
                float bk[6]; ldvec6(s + S_IB + b*24 + 8, bk);
                float k0[6], k1[6], k2[6];
                #pragma unroll
                for (int j = 0; j < 6; j++) {
                    float w[6]; ldvec6(iwb + (6+j)*8, w);
                    k0[j] = bk[j] + dot6r(w, z0);
                    k1[j] = bk[j] + dot6r(w, z1);
                    k2[j] = bk[j] + dot6r(w, z2);
                }
                *(float4*)(tile + r0*12)     = make_float4(k0[0],k0[1],k0[2],k0[3]);
                *(float2*)(tile + r0*12 + 4) = make_float2(k0[4],k0[5]);
                *(float4*)(tile + r1*12)     = make_float4(k1[0],k1[1],k1[2],k1[3]);
                *(float2*)(tile + r1*12 + 4) = make_float2(k1[4],k1[5]);
                *(float4*)(tile + r2*12)     = make_float4(k2[0],k2[1],k2[2],k2[3]);
                *(float2*)(tile + r2*12 + 4) = make_float2(k2[4],k2[5]);
            }
            // v projection -> store rows
            {
                float bv[6]; ldvec6(s + S_IB + b*24 + 16, bv);
                float v0[6], v1[6], v2[6];
                #pragma unroll
                for (int j = 0; j < 6; j++) {
                    float w[6]; ldvec6(iwb + (12+j)*8, w);
                    v0[j] = bv[j] + dot6r(w, z0);
                    v1[j] = bv[j] + dot6r(w, z1);
                    v2[j] = bv[j] + dot6r(w, z2);
                }
                *(float2*)(tile + r0*12 + 6) = make_float2(v0[0],v0[1]);
                *(float4*)(tile + r0*12 + 8) = make_float4(v0[2],v0[3],v0[4],v0[5]);
                *(float2*)(tile + r1*12 + 6) = make_float2(v1[0],v1[1]);
                *(float4*)(tile + r1*12 + 8) = make_float4(v1[2],v1[3],v1[4],v1[5]);
                *(float2*)(tile + r2*12 + 6) = make_float2(v2[0],v2[1]);
                *(float4*)(tile + r2*12 + 8) = make_float4(v2[2],v2[3],v2[4],v2[5]);
            }
        }
        __syncthreads();   // tiles complete

        if (act) {
            // online softmax-attention via EX2 over 3 query rows per thread.
            // No max-subtraction: LN bounds the scores, EX2 cannot overflow.
            float l0 = 0.f, l1 = 0.f, l2 = 0.f;
            float a0[6] = {0,0,0,0,0,0}, a1[6] = {0,0,0,0,0,0}, a2[6] = {0,0,0,0,0,0};
            #pragma unroll 3
            for (int kk = 0; kk < SEQ; kk++) {
                const float4 A = *(const float4*)(tile + kk*12);
                const float4 B = *(const float4*)(tile + kk*12 + 4);
                const float4 C = *(const float4*)(tile + kk*12 + 8);
                float s0 = fmaf(q0[0], A.x, q0[1]*A.y);
                float s1 = fmaf(q1[0], A.x, q1[1]*A.y);
                float s2 = fmaf(q2[0], A.x, q2[1]*A.y);
                s0 = fmaf(q0[2], A.z, s0); s1 = fmaf(q1[2], A.z, s1); s2 = fmaf(q2[2], A.z, s2);
                s0 = fmaf(q0[3], A.w, s0); s1 = fmaf(q1[3], A.w, s1); s2 = fmaf(q2[3], A.w, s2);
                s0 = fmaf(q0[4], B.x, s0); s1 = fmaf(q1[4], B.x, s1); s2 = fmaf(q2[4], B.x, s2);
                s0 = fmaf(q0[5], B.y, s0); s1 = fmaf(q1[5], B.y, s1); s2 = fmaf(q2[5], B.y, s2);
                float e0 = ex2(s0), e1 = ex2(s1), e2 = ex2(s2);
                l0 += e0; l1 += e1; l2 += e2;
                a0[0] = fmaf(e0, B.z, a0[0]); a1[0] = fmaf(e1, B.z, a1[0]); a2[0] = fmaf(e2, B.z, a2[0]);
                a0[1] = fmaf(e0, B.w, a0[1]); a1[1] = fmaf(e1, B.w, a1[1]); a2[1] = fmaf(e2, B.w, a2[1]);
                a0[2] = fmaf(e0, C.x, a0[2]); a1[2] = fmaf(e1, C.x, a1[2]); a2[2] = fmaf(e2, C.x, a2[2]);
                a0[3] = fmaf(e0, C.y, a0[3]); a1[3] = fmaf(e1, C.y, a1[3]); a2[3] = fmaf(e2, C.y, a2[3]);
                a0[4] = fmaf(e0, C.z, a0[4]); a1[4] = fmaf(e1, C.z, a1[4]); a2[4] = fmaf(e2, C.z, a2[4]);
                a0[5] = fmaf(e0, C.w, a0[5]); a1[5] = fmaf(e1, C.w, a1[5]); a2[5] = fmaf(e2, C.w, a2[5]);
            }

            // out projection + ELU + residual (weight-row-major over 3 rows)
            float o0[6], o1[6], o2[6];
            {
                float rl0 = __fdividef(1.f, l0);
                float rl1 = __fdividef(1.f, l1);
                float rl2 = __fdividef(1.f, l2);
                #pragma unroll
                for (int d = 0; d < 6; d++) { o0[d] = a0[d]*rl0; o1[d] = a1[d]*rl1; o2[d] = a2[d]*rl2; }
            }
            {
                float bo[6]; ldvec6(s + S_OB + b*8, bo);
                #pragma unroll
                for (int j = 0; j < 6; j++) {
                    float w[6]; ldvec6(owb + j*8, w);
                    h0[j] += elu(bo[j] + dot6r(w, o0));
                    h1[j] += elu(bo[j] + dot6r(w, o1));
                    h2[j] += elu(bo[j] + dot6r(w, o2));
                }
            }
        }
    }

    // ---- heads ----
    __syncthreads();   // final attention reads complete; tiles become f-buffers
    if (act) {
        float* fs = tile;
        #pragma unroll
        for (int d = 0; d < 6; d += 2) *(float2*)(fs + r0*6 + d) = make_float2(h0[d], h0[d+1]);
        #pragma unroll
        for (int d = 0; d < 6; d += 2) *(float2*)(fs + r1*6 + d) = make_float2(h1[d], h1[d+1]);
        #pragma unroll
        for (int d = 0; d < 6; d += 2) *(float2*)(fs + r2*6 + d) = make_float2(h2[d], h2[d+1]);
    }
    __syncthreads();

    const int warp = tid >> 5, lane = tid & 31;
    for (int ee = warp; ee < ELEMS; ee += 4) {
        const int bi = blockIdx.x * ELEMS + ee;
        if (bi >= BATCH) break;
        const float* fs = s + S_KV + ee * TSTRIDE;

        float av = 0.f;
        float ap[12] = {0,0,0,0,0,0,0,0,0,0,0,0};
        for (int i = lane; i < SEQ*DIM; i += 32) {
            float fv = fs[i];
            av = fmaf(fv, __ldg(vw + i), av);
            #pragma unroll
            for (int j = 0; j < 12; j++) ap[j] = fmaf(fv, __ldg(pw + j*(SEQ*DIM) + i), ap[j]);
        }
        #pragma unroll
        for (int off = 16; off > 0; off >>= 1) {
            av += __shfl_xor_sync(0xffffffffu, av, off);
            #pragma unroll
            for (int j = 0; j < 12; j++) ap[j] += __shfl_xor_sync(0xffffffffu, ap[j], off);
        }
        av += __ldg(vb);
        #pragma unroll
        for (int j = 0; j < 12; j++) ap[j] += __ldg(pb + j);

        float m = ap[0];
        #pragma unroll
        for (int j = 1; j < 12; j++) m = fmaxf(m, ap[j]);
        float sum = 0.f;
        #pragma unroll
        for (int j = 0; j < 12; j++) sum += __expf(ap[j] - m);
        float rs = __fdividef(1.f, sum);

        if (lane == 0) out[bi] = av;
        #pragma unroll
        for (int j = 0; j < 12; j++) {
            if (lane == j) out[BATCH + (size_t)bi*12 + j] = __expf(ap[j] - m) * rs;
        }
    }
}

extern "C" void kernel_launch(void* const* d_in, const int* in_sizes, int n_in,
                              void* d_out, int out_size)
{
    (void)in_sizes; (void)n_in; (void)out_size;
    const float* x  = (const float*)d_in[0];
    const float* ew = (const float*)d_in[1];
    const float* eb = (const float*)d_in[2];
    const float* fw = (const float*)d_in[3];
    const float* fb = (const float*)d_in[4];
    const float* lg = (const float*)d_in[5];
    const float* lb = (const float*)d_in[6];
    const float* iw = (const float*)d_in[7];
    const float* ib = (const float*)d_in[8];
    const float* ow = (const float*)d_in[9];
    const float* ob = (const float*)d_in[10];
    const float* vw = (const float*)d_in[11];
    const float* vb = (const float*)d_in[12];
    const float* pw = (const float*)d_in[13];
    const float* pb = (const float*)d_in[14];
    float* out = (float*)d_out;

    const int grid = (BATCH + ELEMS - 1) / ELEMS;   // 9363
    rubik_kernel<<<grid, THREADS>>>(x, ew, eb, fw, fb, lg, lb,
                                    iw, ib, ow, ob, vw, vb, pw, pb, out);
}

// round 6
// speedup vs baseline: 1.4157x; 1.0088x over previous
#include <cuda_runtime.h>

#define NB      8
#define BATCH   65536
#define SEQ     54
#define DIM     6
#define EPS     1e-5f

#define THREADS 128
#define ELEMS   7            // batch elements per CTA
#define TPE     18           // threads per element (3 rows each: r, r+18, r+36)
#define ACTIVE  (ELEMS*TPE)  // 126

// ---------------- shared layout (floats) ----------------
#define S_EW 0        // embed_w  [6][8]            -> 48
#define S_EB 48       // embed_b  [8]               -> 56
#define S_FW 56       // fc1_w    [8][6][8]   (384) -> 440
#define S_FB 440      // fc1_b    [8][8]      (64)  -> 504
#define S_LG 504      // ln_g     [8][8]      (64)  -> 568
#define S_LB 568      // ln_b     [8][8]      (64)  -> 632
#define S_IW 632      // inproj_w [8][18][8] (1152) -> 1784
#define S_IB 1784     // inproj_b [8][3][8]  (192)  -> 1976  (q/k/v bias rows)
#define S_OW 1976     // out_w    [8][6][8]  (384)  -> 2360
#define S_OB 2360     // out_b    [8][8]     (64)   -> 2424
#define S_KV 2424     // 7 tiles of TSTRIDE; tile = kv-packed [54][12]
#define TSTRIDE 664   // 648 + 16 pad; stride%32==24 -> distinct bank groups per warp
#define S_TOTAL (S_KV + ELEMS * TSTRIDE)   // 7072 floats = 28288 B

typedef unsigned long long u64;

// ---- packed f32x2 primitives (sm_100+: SASS FFMA2, double-rate fp32) ----
__device__ __forceinline__ u64 pk2(float lo, float hi) {
    u64 r;
    asm("mov.b64 %0, {%1, %2};" : "=l"(r)
        : "r"(__float_as_uint(lo)), "r"(__float_as_uint(hi)));
    return r;
}
__device__ __forceinline__ void upk2(u64 p, float& lo, float& hi) {
    unsigned a, b;
    asm("mov.b64 {%0, %1}, %2;" : "=r"(a), "=r"(b) : "l"(p));
    lo = __uint_as_float(a); hi = __uint_as_float(b);
}
__device__ __forceinline__ u64 mul2(u64 a, u64 b) {
    u64 d; asm("mul.rn.f32x2 %0, %1, %2;" : "=l"(d) : "l"(a), "l"(b)); return d;
}
__device__ __forceinline__ u64 fma2(u64 a, u64 b, u64 c) {
    u64 d; asm("fma.rn.f32x2 %0, %1, %2, %3;" : "=l"(d) : "l"(a), "l"(b), "l"(c)); return d;
}
__device__ __forceinline__ float hadd2(u64 p) { float lo, hi; upk2(p, lo, hi); return lo + hi; }

// packed dot over 6 elements (3 pairs): 3 packed FMA + horizontal add
__device__ __forceinline__ float dot6p(const u64 w[3], const u64 h[3]) {
    u64 p = mul2(w[0], h[0]);
    p = fma2(w[1], h[1], p);
    p = fma2(w[2], h[2], p);
    return hadd2(p);
}

// load an 8-float-padded weight row (32B aligned) as 3 packed pairs (2 LDS)
__device__ __forceinline__ void ldw6p(const float* __restrict__ p, u64 w[3]) {
    ulonglong2 t = *(const ulonglong2*)p;          // (w0,w1),(w2,w3)
    w[0] = t.x; w[1] = t.y;
    w[2] = *(const u64*)(p + 4);                   // (w4,w5)
}

__device__ __forceinline__ void ldvec6(const float* __restrict__ p, float v[6]) {
    float4 a = *(const float4*)p;
    float2 b = *(const float2*)(p + 4);
    v[0]=a.x; v[1]=a.y; v[2]=a.z; v[3]=a.w; v[4]=b.x; v[5]=b.y;
}

__device__ __forceinline__ float dot6r(const float w[6], const float h[6]) {
    float t = w[0]*h[0];
    t = fmaf(w[1], h[1], t);
    t = fmaf(w[2], h[2], t);
    t = fmaf(w[3], h[3], t);
    t = fmaf(w[4], h[4], t);
    t = fmaf(w[5], h[5], t);
    return t;
}

__device__ __forceinline__ float ex2(float x) {
    float y;
    asm("ex2.approx.ftz.f32 %0, %1;" : "=f"(y) : "f"(x));
    return y;
}

__device__ __forceinline__ float elu(float t) {
    return t > 0.f ? t : (__expf(t) - 1.f);
}

__device__ __forceinline__ void ln_row(float z[6], const float g[6], const float b[6]) {
    float mu = (z[0]+z[1]+z[2]+z[3]+z[4]+z[5]) * (1.0f/6.0f);
    float var = 0.f;
    #pragma unroll
    for (int d = 0; d < 6; d++) { float t = z[d] - mu; var = fmaf(t, t, var); }
    float is = rsqrtf(var * (1.0f/6.0f) + EPS);
    #pragma unroll
    for (int d = 0; d < 6; d++) z[d] = (z[d] - mu) * is * g[d] + b[d];
}

__device__ __forceinline__ void pack3(const float v[6], u64 p[3]) {
    p[0] = pk2(v[0], v[1]); p[1] = pk2(v[2], v[3]); p[2] = pk2(v[4], v[5]);
}

__global__ __launch_bounds__(THREADS, 4)
void rubik_kernel(const float* __restrict__ x,
                  const float* __restrict__ ew, const float* __restrict__ eb,
                  const float* __restrict__ fw, const float* __restrict__ fb,
                  const float* __restrict__ lg, const float* __restrict__ lb,
                  const float* __restrict__ iw, const float* __restrict__ ib,
                  const float* __restrict__ ow, const float* __restrict__ ob,
                  const float* __restrict__ vw, const float* __restrict__ vb,
                  const float* __restrict__ pw, const float* __restrict__ pb,
                  float* __restrict__ out)
{
    __shared__ __align__(16) float s[S_TOTAL];
    const int tid = threadIdx.x;

    // ---- stage weights into padded shared layout ----
    for (int t = tid; t < 36;  t += THREADS) s[S_EW + (t/6)*8 + t%6] = ew[t];
    for (int t = tid; t < 6;   t += THREADS) s[S_EB + t] = eb[t];
    for (int t = tid; t < 288; t += THREADS) { int b = t/36; s[S_FW + b*48 + ((t/6)%6)*8 + t%6] = fw[t]; }
    for (int t = tid; t < 48;  t += THREADS) s[S_FB + (t/6)*8 + t%6] = fb[t];
    for (int t = tid; t < 48;  t += THREADS) s[S_LG + (t/6)*8 + t%6] = lg[t];
    for (int t = tid; t < 48;  t += THREADS) s[S_LB + (t/6)*8 + t%6] = lb[t];
    for (int t = tid; t < 864; t += THREADS) { int b = t/108; s[S_IW + b*144 + ((t/6)%18)*8 + t%6] = iw[t]; }
    for (int t = tid; t < 144; t += THREADS) { int b = t/18, j = t%18; s[S_IB + b*24 + (j/6)*8 + j%6] = ib[t]; }
    for (int t = tid; t < 288; t += THREADS) { int b = t/36; s[S_OW + b*48 + ((t/6)%6)*8 + t%6] = ow[t]; }
    for (int t = tid; t < 48;  t += THREADS) s[S_OB + (t/6)*8 + t%6] = ob[t];
    __syncthreads();

    // ---- mapping: 7 elems x 18 threads; each thread owns rows r, r+18, r+36 ----
    const bool act = tid < ACTIVE;
    const int  e   = tid / TPE;
    const int  r0  = tid % TPE, r1 = r0 + 18, r2 = r0 + 36;
    const int  bie = blockIdx.x * ELEMS + e;
    const bool valid = act && (bie < BATCH);
    float* tile = s + S_KV + e * TSTRIDE;

    // ---- load x rows + embed ----
    float h0[6], h1[6], h2[6];
    {
        float xr0[6], xr1[6], xr2[6];
        if (valid) {
            const float* p0 = x + (size_t)bie * (SEQ*DIM) + r0*DIM;
            const float* p1 = x + (size_t)bie * (SEQ*DIM) + r1*DIM;
            const float* p2 = x + (size_t)bie * (SEQ*DIM) + r2*DIM;
            float2 a, b, c;
            a = *(const float2*)(p0); b = *(const float2*)(p0+2); c = *(const float2*)(p0+4);
            xr0[0]=a.x; xr0[1]=a.y; xr0[2]=b.x; xr0[3]=b.y; xr0[4]=c.x; xr0[5]=c.y;
            a = *(const float2*)(p1); b = *(const float2*)(p1+2); c = *(const float2*)(p1+4);
            xr1[0]=a.x; xr1[1]=a.y; xr1[2]=b.x; xr1[3]=b.y; xr1[4]=c.x; xr1[5]=c.y;
            a = *(const float2*)(p2); b = *(const float2*)(p2+2); c = *(const float2*)(p2+4);
            xr2[0]=a.x; xr2[1]=a.y; xr2[2]=b.x; xr2[3]=b.y; xr2[4]=c.x; xr2[5]=c.y;
        } else {
            #pragma unroll
            for (int d = 0; d < 6; d++) { xr0[d]=0.f; xr1[d]=0.f; xr2[d]=0.f; }
        }
        float ebv[6]; ldvec6(s + S_EB, ebv);
        #pragma unroll
        for (int j = 0; j < 6; j++) {
            float w[6]; ldvec6(s + S_EW + j*8, w);
            h0[j] = ebv[j] + dot6r(w, xr0);
            h1[j] = ebv[j] + dot6r(w, xr1);
            h2[j] = ebv[j] + dot6r(w, xr2);
        }
    }

    // ---- 8 transformer blocks ----
    for (int b = 0; b < NB; b++) {
        const float* fwb = s + S_FW + b*48;
        const float* iwb = s + S_IW + b*144;
        const float* owb = s + S_OW + b*48;

        __syncthreads();   // prior block's tile reads done before overwrite

        u64 qp0[3], qp1[3], qp2[3];
        if (act) {
            u64 hp0[3], hp1[3], hp2[3];
            pack3(h0, hp0); pack3(h1, hp1); pack3(h2, hp2);

            // fc1 + ELU (packed dots)
            float z0[6], z1[6], z2[6];
            {
                float bf[6]; ldvec6(s + S_FB + b*8, bf);
                #pragma unroll
                for (int j = 0; j < 6; j++) {
                    u64 w[3]; ldw6p(fwb + j*8, w);
                    z0[j] = elu(bf[j] + dot6p(w, hp0));
                    z1[j] = elu(bf[j] + dot6p(w, hp1));
                    z2[j] = elu(bf[j] + dot6p(w, hp2));
                }
            }
            // LayerNorm
            {
                float g[6], bl[6];
                ldvec6(s + S_LG + b*8, g);
                ldvec6(s + S_LB + b*8, bl);
                ln_row(z0, g, bl); ln_row(z1, g, bl); ln_row(z2, g, bl);
            }
            u64 zp0[3], zp1[3], zp2[3];
            pack3(z0, zp0); pack3(z1, zp1); pack3(z2, zp2);

            // q projection (pre-scaled by log2e/sqrt(6) for EX2)
            {
                const float qs = 0.588978587229f;
                float bq[6]; ldvec6(s + S_IB + b*24, bq);
                float q0[6], q1[6], q2[6];
                #pragma unroll
                for (int j = 0; j < 6; j++) {
                    u64 w[3]; ldw6p(iwb + j*8, w);
                    q0[j] = (bq[j] + dot6p(w, zp0)) * qs;
                    q1[j] = (bq[j] + dot6p(w, zp1)) * qs;
                    q2[j] = (bq[j] + dot6p(w, zp2)) * qs;
                }
                pack3(q0, qp0); pack3(q1, qp1); pack3(q2, qp2);
            }
            // k projection -> store rows
            {
                float bk[6]; ldvec6(s + S_IB + b*24 + 8, bk);
                float k0[6], k1[6], k2[6];
                #pragma unroll
                for (int j = 0; j < 6; j++) {
                    u64 w[3]; ldw6p(iwb + (6+j)*8, w);
                    k0[j] = bk[j] + dot6p(w, zp0);
                    k1[j] = bk[j] + dot6p(w, zp1);
                    k2[j] = bk[j] + dot6p(w, zp2);
                }
                *(float4*)(tile + r0*12)     = make_float4(k0[0],k0[1],k0[2],k0[3]);
                *(float2*)(tile + r0*12 + 4) = make_float2(k0[4],k0[5]);
                *(float4*)(tile + r1*12)     = make_float4(k1[0],k1[1],k1[2],k1[3]);
                *(float2*)(tile + r1*12 + 4) = make_float2(k1[4],k1[5]);
                *(float4*)(tile + r2*12)     = make_float4(k2[0],k2[1],k2[2],k2[3]);
                *(float2*)(tile + r2*12 + 4) = make_float2(k2[4],k2[5]);
            }
            // v projection -> store rows
            {
                float bv[6]; ldvec6(s + S_IB + b*24 + 16, bv);
                float v0[6], v1[6], v2[6];
                #pragma unroll
                for (int j = 0; j < 6; j++) {
                    u64 w[3]; ldw6p(iwb + (12+j)*8, w);
                    v0[j] = bv[j] + dot6p(w, zp0);
                    v1[j] = bv[j] + dot6p(w, zp1);
                    v2[j] = bv[j] + dot6p(w, zp2);
                }
                *(float2*)(tile + r0*12 + 6) = make_float2(v0[0],v0[1]);
                *(float4*)(tile + r0*12 + 8) = make_float4(v0[2],v0[3],v0[4],v0[5]);
                *(float2*)(tile + r1*12 + 6) = make_float2(v1[0],v1[1]);
                *(float4*)(tile + r1*12 + 8) = make_float4(v1[2],v1[3],v1[4],v1[5]);
                *(float2*)(tile + r2*12 + 6) = make_float2(v2[0],v2[1]);
                *(float4*)(tile + r2*12 + 8) = make_float4(v2[2],v2[3],v2[4],v2[5]);
            }
        }
        __syncthreads();   // tiles complete

        if (act) {
            // online softmax-attention, fully packed f32x2.
            // tile row = [k0..k5, v0..v5]; 48B-aligned -> reinterpret as packed pairs.
            // No max-subtraction: LN bounds the scores, EX2 cannot overflow.
            float l0 = 0.f, l1 = 0.f, l2 = 0.f;
            u64 ap0[3], ap1[3], ap2[3];
            {
                u64 z = pk2(0.f, 0.f);
                ap0[0]=z; ap0[1]=z; ap0[2]=z;
                ap1[0]=z; ap1[1]=z; ap1[2]=z;
                ap2[0]=z; ap2[1]=z; ap2[2]=z;
            }
            #pragma unroll 3
            for (int kk = 0; kk < SEQ; kk++) {
                const ulonglong2 K = *(const ulonglong2*)(tile + kk*12);      // (k0k1)(k2k3)
                const ulonglong2 M = *(const ulonglong2*)(tile + kk*12 + 4);  // (k4k5)(v0v1)
                const ulonglong2 V = *(const ulonglong2*)(tile + kk*12 + 8);  // (v2v3)(v4v5)
                u64 p0 = mul2(qp0[0], K.x);
                u64 p1 = mul2(qp1[0], K.x);
                u64 p2 = mul2(qp2[0], K.x);
                p0 = fma2(qp0[1], K.y, p0); p1 = fma2(qp1[1], K.y, p1); p2 = fma2(qp2[1], K.y, p2);
                p0 = fma2(qp0[2], M.x, p0); p1 = fma2(qp1[2], M.x, p1); p2 = fma2(qp2[2], M.x, p2);
                float e0 = ex2(hadd2(p0));
                float e1 = ex2(hadd2(p1));
                float e2 = ex2(hadd2(p2));
                l0 += e0; l1 += e1; l2 += e2;
                u64 ep0 = pk2(e0, e0), ep1 = pk2(e1, e1), ep2 = pk2(e2, e2);
                ap0[0] = fma2(ep0, M.y, ap0[0]); ap1[0] = fma2(ep1, M.y, ap1[0]); ap2[0] = fma2(ep2, M.y, ap2[0]);
                ap0[1] = fma2(ep0, V.x, ap0[1]); ap1[1] = fma2(ep1, V.x, ap1[1]); ap2[1] = fma2(ep2, V.x, ap2[1]);
                ap0[2] = fma2(ep0, V.y, ap0[2]); ap1[2] = fma2(ep1, V.y, ap1[2]); ap2[2] = fma2(ep2, V.y, ap2[2]);
            }

            // normalize, out projection + ELU + residual (packed dots)
            u64 op0[3], op1[3], op2[3];
            {
                float rl0 = __fdividef(1.f, l0);
                float rl1 = __fdividef(1.f, l1);
                float rl2 = __fdividef(1.f, l2);
                u64 rp0 = pk2(rl0, rl0), rp1 = pk2(rl1, rl1), rp2 = pk2(rl2, rl2);
                #pragma unroll
                for (int i = 0; i < 3; i++) {
                    op0[i] = mul2(ap0[i], rp0);
                    op1[i] = mul2(ap1[i], rp1);
                    op2[i] = mul2(ap2[i], rp2);
                }
            }
            {
                float bo[6]; ldvec6(s + S_OB + b*8, bo);
                #pragma unroll
                for (int j = 0; j < 6; j++) {
                    u64 w[3]; ldw6p(owb + j*8, w);
                    h0[j] += elu(bo[j] + dot6p(w, op0));
                    h1[j] += elu(bo[j] + dot6p(w, op1));
                    h2[j] += elu(bo[j] + dot6p(w, op2));
                }
            }
        }
    }

    // ---- heads ----
    __syncthreads();   // final attention reads complete; tiles become f-buffers
    if (act) {
        float* fs = tile;
        #pragma unroll
        for (int d = 0; d < 6; d += 2) *(float2*)(fs + r0*6 + d) = make_float2(h0[d], h0[d+1]);
        #pragma unroll
        for (int d = 0; d < 6; d += 2) *(float2*)(fs + r1*6 + d) = make_float2(h1[d], h1[d+1]);
        #pragma unroll
        for (int d = 0; d < 6; d += 2) *(float2*)(fs + r2*6 + d) = make_float2(h2[d], h2[d+1]);
    }
    __syncthreads();

    const int warp = tid >> 5, lane = tid & 31;
    for (int ee = warp; ee < ELEMS; ee += 4) {
        const int bi = blockIdx.x * ELEMS + ee;
        if (bi >= BATCH) break;
        const float* fs = s + S_KV + ee * TSTRIDE;

        float av = 0.f;
        float ap[12] = {0,0,0,0,0,0,0,0,0,0,0,0};
        for (int i = lane; i < SEQ*DIM; i += 32) {
            float fv = fs[i];
            av = fmaf(fv, __ldg(vw + i), av);
            #pragma unroll
            for (int j = 0; j < 12; j++) ap[j] = fmaf(fv, __ldg(pw + j*(SEQ*DIM) + i), ap[j]);
        }
        #pragma unroll
        for (int off = 16; off > 0; off >>= 1) {
            av += __shfl_xor_sync(0xffffffffu, av, off);
            #pragma unroll
            for (int j = 0; j < 12; j++) ap[j] += __shfl_xor_sync(0xffffffffu, ap[j], off);
        }
        av += __ldg(vb);
        #pragma unroll
        for (int j = 0; j < 12; j++) ap[j] += __ldg(pb + j);

        float m = ap[0];
        #pragma unroll
        for (int j = 1; j < 12; j++) m = fmaxf(m, ap[j]);
        float sum = 0.f;
        #pragma unroll
        for (int j = 0; j < 12; j++) sum += __expf(ap[j] - m);
        float rs = __fdividef(1.f, sum);

        if (lane == 0) out[bi] = av;
        #pragma unroll
        for (int j = 0; j < 12; j++) {
            if (lane == j) out[BATCH + (size_t)bi*12 + j] = __expf(ap[j] - m) * rs;
        }
    }
}

extern "C" void kernel_launch(void* const* d_in, const int* in_sizes, int n_in,
                              void* d_out, int out_size)
{
    (void)in_sizes; (void)n_in; (void)out_size;
    const float* x  = (const float*)d_in[0];
    const float* ew = (const float*)d_in[1];
    const float* eb = (const float*)d_in[2];
    const float* fw = (const float*)d_in[3];
    const float* fb = (const float*)d_in[4];
    const float* lg = (const float*)d_in[5];
    const float* lb = (const float*)d_in[6];
    const float* iw = (const float*)d_in[7];
    const float* ib = (const float*)d_in[8];
    const float* ow = (const float*)d_in[9];
    const float* ob = (const float*)d_in[10];
    const float* vw = (const float*)d_in[11];
    const float* vb = (const float*)d_in[12];
    const float* pw = (const float*)d_in[13];
    const float* pb = (const float*)d_in[14];
    float* out = (float*)d_out;

    const int grid = (BATCH + ELEMS - 1) / ELEMS;   // 9363
    rubik_kernel<<<grid, THREADS>>>(x, ew, eb, fw, fb, lg, lb,
                                    iw, ib, ow, ob, vw, vb, pw, pb, out);
}